// round 13
// baseline (speedup 1.0000x reference)
#include <cuda_runtime.h>
#include <cuda_fp16.h>
#include <cstdint>
#include <cstddef>

#define SEQ   4096
#define HID   1024
#define BATCH 4
#define MTOT  (BATCH * SEQ)

#define KC 64                            // K elements per chunk
#define BM 128                           // CTA tile M
#define BN 256                           // CTA tile N
#define TILE_A (BM * KC * 2)             // 16 KB (one A tile)
#define TILE_BN (BN * KC * 2)            // 32 KB (B tile)
#define EPI_BYTES (BM * 260 * 4)         // 133,120 B fp32 epilogue tile
#define DYN_SMEM (EPI_BYTES + 1024)      // >= 2*(2*TILE_A+TILE_BN)=128K too
#define NTHREADS 256

// ---------------- scratch (device globals; no runtime alloc) ----------------
__device__ __half g_xh[(size_t)MTOT * HID], g_xl[(size_t)MTOT * HID];
__device__ __half g_wh[(size_t)3 * HID * HID];                    // W truncated
__device__ __half g_qh[(size_t)MTOT * HID], g_ql[(size_t)MTOT * HID];
__device__ __half g_kh[(size_t)MTOT * HID];                       // K truncated
__device__ __half g_vth[(size_t)MTOT * HID];                      // V^T truncated [b][h][s]
__device__ float  g_s[(size_t)BATCH * SEQ * SEQ];
__device__ __half g_ph[(size_t)BATCH * SEQ * SEQ];                // P truncated

// ---------------- helpers (base-target PTX only) ----------------
__device__ __forceinline__ uint32_t smem_u32(const void* p) {
    return (uint32_t)__cvta_generic_to_shared(p);
}
__device__ __forceinline__ uint32_t sw128(uint32_t o) { return o ^ ((o >> 3) & 0x70); }

__device__ __forceinline__ void cp16(uint32_t dst, const void* src) {
    asm volatile("cp.async.cg.shared.global [%0], [%1], 16;" :: "r"(dst), "l"(src) : "memory");
}
__device__ __forceinline__ void cp_commit() {
    asm volatile("cp.async.commit_group;" ::: "memory");
}
template <int N>
__device__ __forceinline__ void cp_wait() {
    asm volatile("cp.async.wait_group %0;" :: "n"(N) : "memory");
}
__device__ __forceinline__ void ldsm4(uint32_t& r0, uint32_t& r1, uint32_t& r2, uint32_t& r3,
                                      uint32_t addr) {
    asm volatile("ldmatrix.sync.aligned.m8n8.x4.shared.b16 {%0,%1,%2,%3}, [%4];"
                 : "=r"(r0), "=r"(r1), "=r"(r2), "=r"(r3) : "r"(addr));
}
__device__ __forceinline__ void mma4(float (&d)[4], const uint32_t (&a)[4], const uint32_t (&b)[2]) {
    asm volatile(
        "mma.sync.aligned.m16n8k16.row.col.f32.f16.f16.f32 "
        "{%0,%1,%2,%3}, {%4,%5,%6,%7}, {%8,%9}, {%0,%1,%2,%3};"
        : "+f"(d[0]), "+f"(d[1]), "+f"(d[2]), "+f"(d[3])
        : "r"(a[0]), "r"(a[1]), "r"(a[2]), "r"(a[3]), "r"(b[0]), "r"(b[1]));
}

// ---------------- tile load: ROWS x 64 fp16 (128 B rows), SW128, cp.async ----------------
template <int ROWS>
__device__ __forceinline__ void tile_cp(uint32_t dstbase, const __half* __restrict__ g,
                                        int ld, int row0, int k0, int tid) {
    #pragma unroll
    for (int it = 0; it < ROWS * 8 / NTHREADS; it++) {
        int x = it * NTHREADS + tid;
        int r = x >> 3, c8 = x & 7;
        cp16(dstbase + sw128((uint32_t)(r * 128 + c8 * 16)),
             g + (size_t)(row0 + r) * ld + k0 + c8 * 8);
    }
}

// SPLIT_A: 1 -> A = Ah+Al (2 MMAs), 0 -> A = Ah only (1 MMA)
template <bool SPLIT_A>
__device__ __forceinline__ void stage_load(
    uint32_t sbase,
    const __half* Ah, const __half* Al, int lda, int arow,
    const __half* Bh, int ldb, int brow,
    int k0, int tid)
{
    tile_cp<BM>(sbase, Ah, lda, arow, k0, tid);
    if (SPLIT_A) tile_cp<BM>(sbase + TILE_A, Al, lda, arow, k0, tid);
    tile_cp<BN>(sbase + (SPLIT_A ? 2 : 1) * TILE_A, Bh, ldb, brow, k0, tid);
}

// ---------------- compute one 64-K chunk; warp tile 64x64, 8 warps (2m x 4n) ----------------
template <bool SPLIT_A>
__device__ __forceinline__ void compute_chunk(uint32_t sstage, int wm, int wn, int lane,
                                              float (&acc)[4][8][4])
{
    const uint32_t aBase  = sstage;
    const uint32_t alBase = sstage + TILE_A;
    const uint32_t bBase  = sstage + (SPLIT_A ? 2 : 1) * TILE_A;
    const int rowSel = lane & 15;
    const int colSel = (lane >> 4) * 16;

    #pragma unroll
    for (int kk = 0; kk < 4; kk++) {
        uint32_t ah[4][4], al[4][4];
        #pragma unroll
        for (int mt = 0; mt < 4; mt++) {
            int row = wm * 64 + mt * 16 + rowSel;
            uint32_t off = sw128((uint32_t)(row * 128 + kk * 32 + colSel));
            ldsm4(ah[mt][0], ah[mt][1], ah[mt][2], ah[mt][3], aBase + off);
            if (SPLIT_A)
                ldsm4(al[mt][0], al[mt][1], al[mt][2], al[mt][3], alBase + off);
        }
        uint32_t bh[8][2];
        #pragma unroll
        for (int p = 0; p < 4; p++) {
            int row = wn * 64 + p * 16 + rowSel;
            uint32_t off = sw128((uint32_t)(row * 128 + kk * 32 + colSel));
            uint32_t r0, r1, r2, r3;
            ldsm4(r0, r1, r2, r3, bBase + off);
            bh[p * 2][0] = r0; bh[p * 2][1] = r2;
            bh[p * 2 + 1][0] = r1; bh[p * 2 + 1][1] = r3;
        }
        #pragma unroll
        for (int mt = 0; mt < 4; mt++)
            #pragma unroll
            for (int nt = 0; nt < 8; nt++) {
                mma4(acc[mt][nt], ah[mt], bh[nt]);
                if (SPLIT_A) mma4(acc[mt][nt], al[mt], bh[nt]);
            }
    }
}

// ---------------- mainloop: 2-stage double buffer ----------------
template <bool SPLIT_A>
__device__ __forceinline__ void gemm_main(
    const __half* Ah, const __half* Al, int lda, int arow,
    const __half* Bh, int ldb, int brow,
    int nchunks, uint32_t smb, float (&acc)[4][8][4])
{
    constexpr uint32_t SB = (SPLIT_A ? 2 : 1) * TILE_A + TILE_BN;
    const int tid = threadIdx.x;
    const int wid = tid >> 5;
    const int wm = wid >> 2;             // 0..1
    const int wn = wid & 3;              // 0..3
    const int lane = tid & 31;

    stage_load<SPLIT_A>(smb,      Ah, Al, lda, arow, Bh, ldb, brow, 0,  tid); cp_commit();
    stage_load<SPLIT_A>(smb + SB, Ah, Al, lda, arow, Bh, ldb, brow, KC, tid); cp_commit();

    for (int i = 0; i < nchunks; i++) {
        cp_wait<1>();
        __syncthreads();
        compute_chunk<SPLIT_A>(smb + (uint32_t)(i & 1) * SB, wm, wn, lane, acc);
        __syncthreads();
        if (i + 2 < nchunks)
            stage_load<SPLIT_A>(smb + (uint32_t)(i & 1) * SB,
                                Ah, Al, lda, arow, Bh, ldb, brow, (i + 2) * KC, tid);
        cp_commit();
    }
    __syncthreads();
}

// epilogue: accum fragments -> padded fp32 smem tile (row-major, pitch 260)
#define EPITCH 260
__device__ __forceinline__ void acc_to_smem(float* sf, int tid, float (&acc)[4][8][4])
{
    const int wid = tid >> 5;
    const int wm = wid >> 2;
    const int wn = wid & 3;
    const int lane = tid & 31;
    #pragma unroll
    for (int mt = 0; mt < 4; mt++)
        #pragma unroll
        for (int nt = 0; nt < 8; nt++) {
            int r = wm * 64 + mt * 16 + (lane >> 2);
            int c = wn * 64 + nt * 8 + (lane & 3) * 2;
            *reinterpret_cast<float2*>(&sf[r * EPITCH + c]) =
                make_float2(acc[mt][nt][0], acc[mt][nt][1]);
            *reinterpret_cast<float2*>(&sf[(r + 8) * EPITCH + c]) =
                make_float2(acc[mt][nt][2], acc[mt][nt][3]);
        }
}

#define GEMM_PROLOGUE()                                                 \
    extern __shared__ char smraw[];                                     \
    const uint32_t smb = (smem_u32(smraw) + 1023u) & ~1023u;            \
    char* smA = smraw + (smb - smem_u32(smraw));                        \
    const int tid = threadIdx.x;                                        \
    float acc[4][8][4];                                                 \
    _Pragma("unroll")                                                   \
    for (int i_ = 0; i_ < 4; i_++)                                      \
        _Pragma("unroll")                                               \
        for (int j_ = 0; j_ < 8; j_++)                                  \
            _Pragma("unroll")                                           \
            for (int k_ = 0; k_ < 4; k_++) acc[i_][j_][k_] = 0.f;

// ---------------- K1: QKV projection (z: 0=Q split, 1=K trunc, 2=V^T trunc) ----------------
__global__ __launch_bounds__(NTHREADS, 1) void qkv_mma()
{
    GEMM_PROLOGUE();
    const int n0 = blockIdx.x * BN;
    const int m0 = blockIdx.y * BM;
    const int z  = blockIdx.z;

    gemm_main<true>(g_xh, g_xl, HID, m0,
                    g_wh + (size_t)z * HID * HID, HID, n0,
                    HID / KC, smb, acc);

    float* sf = reinterpret_cast<float*>(smA);
    acc_to_smem(sf, tid, acc);
    __syncthreads();

    if (z == 0) {
        #pragma unroll
        for (int it = 0; it < 64; it++) {
            int e = it * NTHREADS + tid;
            int c2 = e & 127, r = e >> 7;
            int c = 2 * c2;
            float v0 = sf[r * EPITCH + c];
            float v1 = sf[r * EPITCH + c + 1];
            __half2 hv, lv;
            hv.x = __float2half(v0); lv.x = __float2half(v0 - __half2float(hv.x));
            hv.y = __float2half(v1); lv.y = __float2half(v1 - __half2float(hv.y));
            *reinterpret_cast<__half2*>(&g_qh[(size_t)(m0 + r) * HID + n0 + c]) = hv;
            *reinterpret_cast<__half2*>(&g_ql[(size_t)(m0 + r) * HID + n0 + c]) = lv;
        }
    } else if (z == 1) {
        #pragma unroll
        for (int it = 0; it < 64; it++) {
            int e = it * NTHREADS + tid;
            int c2 = e & 127, r = e >> 7;
            int c = 2 * c2;
            __half2 hv;
            hv.x = __float2half(sf[r * EPITCH + c]);
            hv.y = __float2half(sf[r * EPITCH + c + 1]);
            *reinterpret_cast<__half2*>(&g_kh[(size_t)(m0 + r) * HID + n0 + c]) = hv;
        }
    } else {
        const int b  = m0 / SEQ;
        const int s0 = m0 % SEQ;
        #pragma unroll
        for (int it = 0; it < 64; it++) {
            int e = it * NTHREADS + tid;
            int r2 = e & 63, c = e >> 6;            // c: 0..255
            __half2 hv;
            hv.x = __float2half(sf[(2 * r2) * EPITCH + c]);
            hv.y = __float2half(sf[(2 * r2 + 1) * EPITCH + c]);
            size_t base = ((size_t)b * HID + n0 + c) * SEQ + s0 + 2 * r2;
            *reinterpret_cast<__half2*>(&g_vth[base]) = hv;
        }
    }
}

// ---------------- K2: scores = (Q K^T)/32, causal tile skip, big tiles first ----------------
__global__ __launch_bounds__(NTHREADS, 1) void scores_mma()
{
    const int n0 = blockIdx.x * BN;
    const int m0 = ((int)gridDim.y - 1 - (int)blockIdx.y) * BM;  // descending work order
    if (n0 >= m0 + BM) return;           // fully masked tile
    const int b = blockIdx.z;

    GEMM_PROLOGUE();

    gemm_main<true>(g_qh + (size_t)b * SEQ * HID, g_ql + (size_t)b * SEQ * HID, HID, m0,
                    g_kh + (size_t)b * SEQ * HID, HID, n0,
                    HID / KC, smb, acc);

    float* sf = reinterpret_cast<float*>(smA);
    acc_to_smem(sf, tid, acc);
    __syncthreads();

    float* dst = g_s + (size_t)b * SEQ * SEQ;
    #pragma unroll
    for (int it = 0; it < 128; it++) {
        int e = it * NTHREADS + tid;
        int c = e & 255, r = e >> 8;
        dst[(size_t)(m0 + r) * SEQ + n0 + c] = sf[r * EPITCH + c] * 0.03125f;
    }
}

// ---------------- K3: softmax; emits P as fp16 + zero pad to tile boundary ----------------
__global__ __launch_bounds__(128) void softmax_kernel()
{
    const int r = blockIdx.x;
    const int b = blockIdx.y;
    const size_t off = (size_t)b * SEQ * SEQ + (size_t)r * SEQ;
    const float* row = g_s + off;
    const int L = r + 1;
    const int t = threadIdx.x;

    float vals[32];
    int cnt = 0;
    float m = -1e30f;
    for (int k = t; k < L; k += 128) {
        float v = row[k];
        vals[cnt++] = v;
        m = fmaxf(m, v);
    }

    __shared__ float red[4];
    #pragma unroll
    for (int o = 16; o; o >>= 1) m = fmaxf(m, __shfl_xor_sync(0xffffffffu, m, o));
    if ((t & 31) == 0) red[t >> 5] = m;
    __syncthreads();
    m = fmaxf(fmaxf(red[0], red[1]), fmaxf(red[2], red[3]));
    __syncthreads();

    float s = 0.f;
    for (int i = 0; i < cnt; i++) {
        float e = __expf(vals[i] - m);
        vals[i] = e;
        s += e;
    }
    #pragma unroll
    for (int o = 16; o; o >>= 1) s += __shfl_xor_sync(0xffffffffu, s, o);
    if ((t & 31) == 0) red[t >> 5] = s;
    __syncthreads();
    s = red[0] + red[1] + red[2] + red[3];

    const float inv = 1.0f / s;
    cnt = 0;
    for (int k = t; k < L; k += 128)
        g_ph[off + k] = __float2half(vals[cnt++] * inv);

    const __half z = __float2half(0.f);
    const int Lpad = (r & ~(BM - 1)) + BM;
    for (int k = L + t; k < Lpad; k += 128)
        g_ph[off + k] = z;
}

// ---------------- K4: O = P V (single-term), K truncated at causal boundary ----------------
__global__ __launch_bounds__(NTHREADS, 1) void pv_mma(float* __restrict__ out)
{
    GEMM_PROLOGUE();
    const int n0 = blockIdx.x * BN;
    const int m0 = ((int)gridDim.y - 1 - (int)blockIdx.y) * BM;  // big tiles first
    const int b  = blockIdx.z;
    const int nchunks = (m0 + BM) / KC;

    gemm_main<false>(g_ph + (size_t)b * SEQ * SEQ, nullptr, SEQ, m0,
                     g_vth + (size_t)b * HID * SEQ, SEQ, n0,
                     nchunks, smb, acc);

    float* sf = reinterpret_cast<float*>(smA);
    acc_to_smem(sf, tid, acc);
    __syncthreads();

    float* dst = out + (size_t)b * SEQ * HID;
    #pragma unroll
    for (int it = 0; it < 128; it++) {
        int e = it * NTHREADS + tid;
        int c = e & 255, r = e >> 8;
        dst[(size_t)(m0 + r) * HID + n0 + c] = sf[r * EPITCH + c];
    }
}

// ---------------- K0a: fp32 -> (hi, lo) fp16 split ----------------
__global__ __launch_bounds__(256) void convert_split_kernel(const float* __restrict__ src,
                                                            __half* __restrict__ hi,
                                                            __half* __restrict__ lo, int n)
{
    int i = (blockIdx.x * 256 + threadIdx.x) * 4;
    if (i >= n) return;
    float4 v = *reinterpret_cast<const float4*>(src + i);
    __half2 h0, h1, l0, l1;
    h0.x = __float2half(v.x); l0.x = __float2half(v.x - __half2float(h0.x));
    h0.y = __float2half(v.y); l0.y = __float2half(v.y - __half2float(h0.y));
    h1.x = __float2half(v.z); l1.x = __float2half(v.z - __half2float(h1.x));
    h1.y = __float2half(v.w); l1.y = __float2half(v.w - __half2float(h1.y));
    *reinterpret_cast<__half2*>(hi + i)     = h0;
    *reinterpret_cast<__half2*>(hi + i + 2) = h1;
    *reinterpret_cast<__half2*>(lo + i)     = l0;
    *reinterpret_cast<__half2*>(lo + i + 2) = l1;
}

// ---------------- K0b: fp32 -> fp16 truncate (round-nearest) ----------------
__global__ __launch_bounds__(256) void convert_trunc_kernel(const float* __restrict__ src,
                                                            __half* __restrict__ hi, int n)
{
    int i = (blockIdx.x * 256 + threadIdx.x) * 4;
    if (i >= n) return;
    float4 v = *reinterpret_cast<const float4*>(src + i);
    __half2 h0, h1;
    h0.x = __float2half(v.x); h0.y = __float2half(v.y);
    h1.x = __float2half(v.z); h1.y = __float2half(v.w);
    *reinterpret_cast<__half2*>(hi + i)     = h0;
    *reinterpret_cast<__half2*>(hi + i + 2) = h1;
}

// ---------------- launch ----------------
extern "C" void kernel_launch(void* const* d_in, const int* in_sizes, int n_in,
                              void* d_out, int out_size)
{
    const float* x  = (const float*)d_in[0];
    const float* Wq = (const float*)d_in[1];
    const float* Wk = (const float*)d_in[2];
    const float* Wv = (const float*)d_in[3];
    float* out = (float*)d_out;

    cudaFuncSetAttribute(qkv_mma,    cudaFuncAttributeMaxDynamicSharedMemorySize, DYN_SMEM);
    cudaFuncSetAttribute(scores_mma, cudaFuncAttributeMaxDynamicSharedMemorySize, DYN_SMEM);
    cudaFuncSetAttribute(pv_mma,     cudaFuncAttributeMaxDynamicSharedMemorySize, DYN_SMEM);

    __half *xh, *xl, *wh;
    cudaGetSymbolAddress((void**)&xh, g_xh);
    cudaGetSymbolAddress((void**)&xl, g_xl);
    cudaGetSymbolAddress((void**)&wh, g_wh);

    const int nx = MTOT * HID;
    const int nw = HID * HID;
    convert_split_kernel<<<nx / 1024, 256>>>(x,  xh, xl, nx);
    convert_trunc_kernel<<<nw / 1024, 256>>>(Wq, wh,                  nw);
    convert_trunc_kernel<<<nw / 1024, 256>>>(Wk, wh + (size_t)nw,     nw);
    convert_trunc_kernel<<<nw / 1024, 256>>>(Wv, wh + 2 * (size_t)nw, nw);

    qkv_mma<<<dim3(HID / BN, MTOT / BM, 3), NTHREADS, DYN_SMEM>>>();
    scores_mma<<<dim3(SEQ / BN, SEQ / BM, BATCH), NTHREADS, DYN_SMEM>>>();
    softmax_kernel<<<dim3(SEQ, BATCH), 128>>>();
    pv_mma<<<dim3(HID / BN, SEQ / BM, BATCH), NTHREADS, DYN_SMEM>>>(out);
}

// round 15
// speedup vs baseline: 1.8971x; 1.8971x over previous
#include <cuda_runtime.h>
#include <cuda_fp16.h>
#include <cstdint>
#include <cstddef>

#define SEQ   4096
#define HID   1024
#define BATCH 4
#define MTOT  (BATCH * SEQ)

#define KC 64                            // K elements per chunk
#define BM 128                           // CTA tile M
#define BN 256                           // CTA tile N
#define TILE_A (BM * KC * 2)             // 16 KB (one A tile)
#define TILE_BN (BN * KC * 2)            // 32 KB (B tile)
#define EPI_BYTES (BM * 260 * 4)         // 133,120 B fp32 epilogue tile
#define DYN_SMEM (EPI_BYTES + 1024)      // >= 2*(2*TILE_A+TILE_BN)=128K too
#define NTHREADS 256

// ---------------- scratch (device globals; no runtime alloc) ----------------
__device__ __half g_xh[(size_t)MTOT * HID];                       // x truncated
__device__ __half g_wh[(size_t)3 * HID * HID];                    // W truncated
__device__ __half g_qh[(size_t)MTOT * HID], g_ql[(size_t)MTOT * HID];  // Q split (for scores)
__device__ __half g_kh[(size_t)MTOT * HID];                       // K truncated
__device__ __half g_vth[(size_t)MTOT * HID];                      // V^T truncated [b][h][s]
__device__ float  g_s[(size_t)BATCH * SEQ * SEQ];
__device__ __half g_ph[(size_t)BATCH * SEQ * SEQ];                // P truncated

// ---------------- helpers (base-target PTX only) ----------------
__device__ __forceinline__ uint32_t smem_u32(const void* p) {
    return (uint32_t)__cvta_generic_to_shared(p);
}
__device__ __forceinline__ uint32_t sw128(uint32_t o) { return o ^ ((o >> 3) & 0x70); }

__device__ __forceinline__ void cp16(uint32_t dst, const void* src) {
    asm volatile("cp.async.cg.shared.global [%0], [%1], 16;" :: "r"(dst), "l"(src) : "memory");
}
__device__ __forceinline__ void cp_commit() {
    asm volatile("cp.async.commit_group;" ::: "memory");
}
template <int N>
__device__ __forceinline__ void cp_wait() {
    asm volatile("cp.async.wait_group %0;" :: "n"(N) : "memory");
}
__device__ __forceinline__ void ldsm4(uint32_t& r0, uint32_t& r1, uint32_t& r2, uint32_t& r3,
                                      uint32_t addr) {
    asm volatile("ldmatrix.sync.aligned.m8n8.x4.shared.b16 {%0,%1,%2,%3}, [%4];"
                 : "=r"(r0), "=r"(r1), "=r"(r2), "=r"(r3) : "r"(addr));
}
__device__ __forceinline__ void mma4(float (&d)[4], const uint32_t (&a)[4], const uint32_t (&b)[2]) {
    asm volatile(
        "mma.sync.aligned.m16n8k16.row.col.f32.f16.f16.f32 "
        "{%0,%1,%2,%3}, {%4,%5,%6,%7}, {%8,%9}, {%0,%1,%2,%3};"
        : "+f"(d[0]), "+f"(d[1]), "+f"(d[2]), "+f"(d[3])
        : "r"(a[0]), "r"(a[1]), "r"(a[2]), "r"(a[3]), "r"(b[0]), "r"(b[1]));
}

// ---------------- tile load: ROWS x 64 fp16 (128 B rows), SW128, cp.async ----------------
template <int ROWS>
__device__ __forceinline__ void tile_cp(uint32_t dstbase, const __half* __restrict__ g,
                                        int ld, int row0, int k0, int tid) {
    #pragma unroll
    for (int it = 0; it < ROWS * 8 / NTHREADS; it++) {
        int x = it * NTHREADS + tid;
        int r = x >> 3, c8 = x & 7;
        cp16(dstbase + sw128((uint32_t)(r * 128 + c8 * 16)),
             g + (size_t)(row0 + r) * ld + k0 + c8 * 8);
    }
}

// SPLIT_A: 1 -> A = Ah+Al (2 MMAs), 0 -> A = Ah only (1 MMA)
template <bool SPLIT_A>
__device__ __forceinline__ void stage_load(
    uint32_t sbase,
    const __half* Ah, const __half* Al, int lda, int arow,
    const __half* Bh, int ldb, int brow,
    int k0, int tid)
{
    tile_cp<BM>(sbase, Ah, lda, arow, k0, tid);
    if (SPLIT_A) tile_cp<BM>(sbase + TILE_A, Al, lda, arow, k0, tid);
    tile_cp<BN>(sbase + (SPLIT_A ? 2 : 1) * TILE_A, Bh, ldb, brow, k0, tid);
}

// ---------------- compute one 64-K chunk; warp tile 64x64, 8 warps (2m x 4n) ----------------
template <bool SPLIT_A>
__device__ __forceinline__ void compute_chunk(uint32_t sstage, int wm, int wn, int lane,
                                              float (&acc)[4][8][4])
{
    const uint32_t aBase  = sstage;
    const uint32_t alBase = sstage + TILE_A;
    const uint32_t bBase  = sstage + (SPLIT_A ? 2 : 1) * TILE_A;
    const int rowSel = lane & 15;
    const int colSel = (lane >> 4) * 16;

    #pragma unroll
    for (int kk = 0; kk < 4; kk++) {
        uint32_t ah[4][4], al[4][4];
        #pragma unroll
        for (int mt = 0; mt < 4; mt++) {
            int row = wm * 64 + mt * 16 + rowSel;
            uint32_t off = sw128((uint32_t)(row * 128 + kk * 32 + colSel));
            ldsm4(ah[mt][0], ah[mt][1], ah[mt][2], ah[mt][3], aBase + off);
            if (SPLIT_A)
                ldsm4(al[mt][0], al[mt][1], al[mt][2], al[mt][3], alBase + off);
        }
        uint32_t bh[8][2];
        #pragma unroll
        for (int p = 0; p < 4; p++) {
            int row = wn * 64 + p * 16 + rowSel;
            uint32_t off = sw128((uint32_t)(row * 128 + kk * 32 + colSel));
            uint32_t r0, r1, r2, r3;
            ldsm4(r0, r1, r2, r3, bBase + off);
            bh[p * 2][0] = r0; bh[p * 2][1] = r2;
            bh[p * 2 + 1][0] = r1; bh[p * 2 + 1][1] = r3;
        }
        #pragma unroll
        for (int mt = 0; mt < 4; mt++)
            #pragma unroll
            for (int nt = 0; nt < 8; nt++) {
                mma4(acc[mt][nt], ah[mt], bh[nt]);
                if (SPLIT_A) mma4(acc[mt][nt], al[mt], bh[nt]);
            }
    }
}

// ---------------- mainloop: 2-stage double buffer ----------------
template <bool SPLIT_A>
__device__ __forceinline__ void gemm_main(
    const __half* Ah, const __half* Al, int lda, int arow,
    const __half* Bh, int ldb, int brow,
    int nchunks, uint32_t smb, float (&acc)[4][8][4])
{
    constexpr uint32_t SB = (SPLIT_A ? 2 : 1) * TILE_A + TILE_BN;
    const int tid = threadIdx.x;
    const int wid = tid >> 5;
    const int wm = wid >> 2;             // 0..1
    const int wn = wid & 3;              // 0..3
    const int lane = tid & 31;

    stage_load<SPLIT_A>(smb,      Ah, Al, lda, arow, Bh, ldb, brow, 0,  tid); cp_commit();
    stage_load<SPLIT_A>(smb + SB, Ah, Al, lda, arow, Bh, ldb, brow, KC, tid); cp_commit();

    for (int i = 0; i < nchunks; i++) {
        cp_wait<1>();
        __syncthreads();
        compute_chunk<SPLIT_A>(smb + (uint32_t)(i & 1) * SB, wm, wn, lane, acc);
        __syncthreads();
        if (i + 2 < nchunks)
            stage_load<SPLIT_A>(smb + (uint32_t)(i & 1) * SB,
                                Ah, Al, lda, arow, Bh, ldb, brow, (i + 2) * KC, tid);
        cp_commit();
    }
    __syncthreads();
}

// epilogue: accum fragments -> padded fp32 smem tile (row-major, pitch 260)
#define EPITCH 260
__device__ __forceinline__ void acc_to_smem(float* sf, int tid, float (&acc)[4][8][4])
{
    const int wid = tid >> 5;
    const int wm = wid >> 2;
    const int wn = wid & 3;
    const int lane = tid & 31;
    #pragma unroll
    for (int mt = 0; mt < 4; mt++)
        #pragma unroll
        for (int nt = 0; nt < 8; nt++) {
            int r = wm * 64 + mt * 16 + (lane >> 2);
            int c = wn * 64 + nt * 8 + (lane & 3) * 2;
            *reinterpret_cast<float2*>(&sf[r * EPITCH + c]) =
                make_float2(acc[mt][nt][0], acc[mt][nt][1]);
            *reinterpret_cast<float2*>(&sf[(r + 8) * EPITCH + c]) =
                make_float2(acc[mt][nt][2], acc[mt][nt][3]);
        }
}

#define GEMM_PROLOGUE()                                                 \
    extern __shared__ char smraw[];                                     \
    const uint32_t smb = (smem_u32(smraw) + 1023u) & ~1023u;            \
    char* smA = smraw + (smb - smem_u32(smraw));                        \
    const int tid = threadIdx.x;                                        \
    float acc[4][8][4];                                                 \
    _Pragma("unroll")                                                   \
    for (int i_ = 0; i_ < 4; i_++)                                      \
        _Pragma("unroll")                                               \
        for (int j_ = 0; j_ < 8; j_++)                                  \
            _Pragma("unroll")                                           \
            for (int k_ = 0; k_ < 4; k_++) acc[i_][j_][k_] = 0.f;

// ---------------- K1: QKV projection, single-term (z: 0=Q split out, 1=K, 2=V^T) ----------------
__global__ __launch_bounds__(NTHREADS, 1) void qkv_mma()
{
    GEMM_PROLOGUE();
    const int n0 = blockIdx.x * BN;
    const int m0 = blockIdx.y * BM;
    const int z  = blockIdx.z;

    gemm_main<false>(g_xh, nullptr, HID, m0,
                     g_wh + (size_t)z * HID * HID, HID, n0,
                     HID / KC, smb, acc);

    float* sf = reinterpret_cast<float*>(smA);
    acc_to_smem(sf, tid, acc);
    __syncthreads();

    if (z == 0) {
        #pragma unroll
        for (int it = 0; it < 64; it++) {
            int e = it * NTHREADS + tid;
            int c2 = e & 127, r = e >> 7;
            int c = 2 * c2;
            float v0 = sf[r * EPITCH + c];
            float v1 = sf[r * EPITCH + c + 1];
            __half2 hv, lv;
            hv.x = __float2half(v0); lv.x = __float2half(v0 - __half2float(hv.x));
            hv.y = __float2half(v1); lv.y = __float2half(v1 - __half2float(hv.y));
            *reinterpret_cast<__half2*>(&g_qh[(size_t)(m0 + r) * HID + n0 + c]) = hv;
            *reinterpret_cast<__half2*>(&g_ql[(size_t)(m0 + r) * HID + n0 + c]) = lv;
        }
    } else if (z == 1) {
        #pragma unroll
        for (int it = 0; it < 64; it++) {
            int e = it * NTHREADS + tid;
            int c2 = e & 127, r = e >> 7;
            int c = 2 * c2;
            __half2 hv;
            hv.x = __float2half(sf[r * EPITCH + c]);
            hv.y = __float2half(sf[r * EPITCH + c + 1]);
            *reinterpret_cast<__half2*>(&g_kh[(size_t)(m0 + r) * HID + n0 + c]) = hv;
        }
    } else {
        const int b  = m0 / SEQ;
        const int s0 = m0 % SEQ;
        #pragma unroll
        for (int it = 0; it < 64; it++) {
            int e = it * NTHREADS + tid;
            int r2 = e & 63, c = e >> 6;            // c: 0..255
            __half2 hv;
            hv.x = __float2half(sf[(2 * r2) * EPITCH + c]);
            hv.y = __float2half(sf[(2 * r2 + 1) * EPITCH + c]);
            size_t base = ((size_t)b * HID + n0 + c) * SEQ + s0 + 2 * r2;
            *reinterpret_cast<__half2*>(&g_vth[base]) = hv;
        }
    }
}

// ---------------- K2: scores = (Q K^T)/32, Q 2-term, causal tile skip, big tiles first ----------------
__global__ __launch_bounds__(NTHREADS, 1) void scores_mma()
{
    const int n0 = blockIdx.x * BN;
    const int m0 = ((int)gridDim.y - 1 - (int)blockIdx.y) * BM;  // descending work order
    if (n0 >= m0 + BM) return;           // fully masked tile
    const int b = blockIdx.z;

    GEMM_PROLOGUE();

    gemm_main<true>(g_qh + (size_t)b * SEQ * HID, g_ql + (size_t)b * SEQ * HID, HID, m0,
                    g_kh + (size_t)b * SEQ * HID, HID, n0,
                    HID / KC, smb, acc);

    float* sf = reinterpret_cast<float*>(smA);
    acc_to_smem(sf, tid, acc);
    __syncthreads();

    float* dst = g_s + (size_t)b * SEQ * SEQ;
    #pragma unroll
    for (int it = 0; it < 128; it++) {
        int e = it * NTHREADS + tid;
        int c = e & 255, r = e >> 8;
        dst[(size_t)(m0 + r) * SEQ + n0 + c] = sf[r * EPITCH + c] * 0.03125f;
    }
}

// ---------------- K3: softmax; emits P as fp16 + zero pad to tile boundary ----------------
__global__ __launch_bounds__(128) void softmax_kernel()
{
    const int r = blockIdx.x;
    const int b = blockIdx.y;
    const size_t off = (size_t)b * SEQ * SEQ + (size_t)r * SEQ;
    const float* row = g_s + off;
    const int L = r + 1;
    const int t = threadIdx.x;

    float vals[32];
    int cnt = 0;
    float m = -1e30f;
    for (int k = t; k < L; k += 128) {
        float v = row[k];
        vals[cnt++] = v;
        m = fmaxf(m, v);
    }

    __shared__ float red[4];
    #pragma unroll
    for (int o = 16; o; o >>= 1) m = fmaxf(m, __shfl_xor_sync(0xffffffffu, m, o));
    if ((t & 31) == 0) red[t >> 5] = m;
    __syncthreads();
    m = fmaxf(fmaxf(red[0], red[1]), fmaxf(red[2], red[3]));
    __syncthreads();

    float s = 0.f;
    for (int i = 0; i < cnt; i++) {
        float e = __expf(vals[i] - m);
        vals[i] = e;
        s += e;
    }
    #pragma unroll
    for (int o = 16; o; o >>= 1) s += __shfl_xor_sync(0xffffffffu, s, o);
    if ((t & 31) == 0) red[t >> 5] = s;
    __syncthreads();
    s = red[0] + red[1] + red[2] + red[3];

    const float inv = 1.0f / s;
    cnt = 0;
    for (int k = t; k < L; k += 128)
        g_ph[off + k] = __float2half(vals[cnt++] * inv);

    const __half z = __float2half(0.f);
    const int Lpad = (r & ~(BM - 1)) + BM;
    for (int k = L + t; k < Lpad; k += 128)
        g_ph[off + k] = z;
}

// ---------------- K4: O = P V (single-term), K truncated at causal boundary ----------------
__global__ __launch_bounds__(NTHREADS, 1) void pv_mma(float* __restrict__ out)
{
    GEMM_PROLOGUE();
    const int n0 = blockIdx.x * BN;
    const int m0 = ((int)gridDim.y - 1 - (int)blockIdx.y) * BM;  // big tiles first
    const int b  = blockIdx.z;
    const int nchunks = (m0 + BM) / KC;

    gemm_main<false>(g_ph + (size_t)b * SEQ * SEQ, nullptr, SEQ, m0,
                     g_vth + (size_t)b * HID * SEQ, SEQ, n0,
                     nchunks, smb, acc);

    float* sf = reinterpret_cast<float*>(smA);
    acc_to_smem(sf, tid, acc);
    __syncthreads();

    float* dst = out + (size_t)b * SEQ * HID;
    #pragma unroll
    for (int it = 0; it < 128; it++) {
        int e = it * NTHREADS + tid;
        int c = e & 255, r = e >> 8;
        dst[(size_t)(m0 + r) * HID + n0 + c] = sf[r * EPITCH + c];
    }
}

// ---------------- K0: fp32 -> fp16 truncate (round-nearest) ----------------
__global__ __launch_bounds__(256) void convert_trunc_kernel(const float* __restrict__ src,
                                                            __half* __restrict__ hi, int n)
{
    int i = (blockIdx.x * 256 + threadIdx.x) * 4;
    if (i >= n) return;
    float4 v = *reinterpret_cast<const float4*>(src + i);
    __half2 h0, h1;
    h0.x = __float2half(v.x); h0.y = __float2half(v.y);
    h1.x = __float2half(v.z); h1.y = __float2half(v.w);
    *reinterpret_cast<__half2*>(hi + i)     = h0;
    *reinterpret_cast<__half2*>(hi + i + 2) = h1;
}

// ---------------- launch ----------------
extern "C" void kernel_launch(void* const* d_in, const int* in_sizes, int n_in,
                              void* d_out, int out_size)
{
    const float* x  = (const float*)d_in[0];
    const float* Wq = (const float*)d_in[1];
    const float* Wk = (const float*)d_in[2];
    const float* Wv = (const float*)d_in[3];
    float* out = (float*)d_out;

    cudaFuncSetAttribute(qkv_mma,    cudaFuncAttributeMaxDynamicSharedMemorySize, DYN_SMEM);
    cudaFuncSetAttribute(scores_mma, cudaFuncAttributeMaxDynamicSharedMemorySize, DYN_SMEM);
    cudaFuncSetAttribute(pv_mma,     cudaFuncAttributeMaxDynamicSharedMemorySize, DYN_SMEM);

    __half *xh, *wh;
    cudaGetSymbolAddress((void**)&xh, g_xh);
    cudaGetSymbolAddress((void**)&wh, g_wh);

    const int nx = MTOT * HID;
    const int nw = HID * HID;
    convert_trunc_kernel<<<nx / 1024, 256>>>(x,  xh,                  nx);
    convert_trunc_kernel<<<nw / 1024, 256>>>(Wq, wh,                  nw);
    convert_trunc_kernel<<<nw / 1024, 256>>>(Wk, wh + (size_t)nw,     nw);
    convert_trunc_kernel<<<nw / 1024, 256>>>(Wv, wh + 2 * (size_t)nw, nw);

    qkv_mma<<<dim3(HID / BN, MTOT / BM, 3), NTHREADS, DYN_SMEM>>>();
    scores_mma<<<dim3(SEQ / BN, SEQ / BM, BATCH), NTHREADS, DYN_SMEM>>>();
    softmax_kernel<<<dim3(SEQ, BATCH), 128>>>();
    pv_mma<<<dim3(HID / BN, SEQ / BM, BATCH), NTHREADS, DYN_SMEM>>>(out);
}

// round 16
// speedup vs baseline: 2.3187x; 1.2222x over previous
#include <cuda_runtime.h>
#include <cuda_fp16.h>
#include <cstdint>
#include <cstddef>

#define SEQ   4096
#define HID   1024
#define BATCH 4
#define MTOT  (BATCH * SEQ)

#define KC 64                            // K elements per chunk
#define BM 128                           // CTA tile M
#define BN 256                           // CTA tile N
#define TILE_A (BM * KC * 2)             // 16 KB (A tile)
#define TILE_BN (BN * KC * 2)            // 32 KB (B tile)
#define EPI_BYTES (BM * 260 * 4)         // 133,120 B fp32 epilogue tile
#define DYN_SMEM (EPI_BYTES + 1024)      // >= 2*(TILE_A+TILE_BN)=96K too
#define NTHREADS 256

// ---------------- scratch (device globals; no runtime alloc) ----------------
__device__ __half g_xh[(size_t)MTOT * HID];                       // x truncated
__device__ __half g_wh[(size_t)3 * HID * HID];                    // W truncated
__device__ __half g_qh[(size_t)MTOT * HID];                       // Q truncated
__device__ __half g_kh[(size_t)MTOT * HID];                       // K truncated
__device__ __half g_vth[(size_t)MTOT * HID];                      // V^T truncated [b][h][s]
__device__ float  g_s[(size_t)BATCH * SEQ * SEQ];
__device__ __half g_ph[(size_t)BATCH * SEQ * SEQ];                // P truncated

// ---------------- helpers (base-target PTX only) ----------------
__device__ __forceinline__ uint32_t smem_u32(const void* p) {
    return (uint32_t)__cvta_generic_to_shared(p);
}
__device__ __forceinline__ uint32_t sw128(uint32_t o) { return o ^ ((o >> 3) & 0x70); }

__device__ __forceinline__ void cp16(uint32_t dst, const void* src) {
    asm volatile("cp.async.cg.shared.global [%0], [%1], 16;" :: "r"(dst), "l"(src) : "memory");
}
__device__ __forceinline__ void cp_commit() {
    asm volatile("cp.async.commit_group;" ::: "memory");
}
template <int N>
__device__ __forceinline__ void cp_wait() {
    asm volatile("cp.async.wait_group %0;" :: "n"(N) : "memory");
}
__device__ __forceinline__ void ldsm4(uint32_t& r0, uint32_t& r1, uint32_t& r2, uint32_t& r3,
                                      uint32_t addr) {
    asm volatile("ldmatrix.sync.aligned.m8n8.x4.shared.b16 {%0,%1,%2,%3}, [%4];"
                 : "=r"(r0), "=r"(r1), "=r"(r2), "=r"(r3) : "r"(addr));
}
__device__ __forceinline__ void mma4(float (&d)[4], const uint32_t (&a)[4], const uint32_t (&b)[2]) {
    asm volatile(
        "mma.sync.aligned.m16n8k16.row.col.f32.f16.f16.f32 "
        "{%0,%1,%2,%3}, {%4,%5,%6,%7}, {%8,%9}, {%0,%1,%2,%3};"
        : "+f"(d[0]), "+f"(d[1]), "+f"(d[2]), "+f"(d[3])
        : "r"(a[0]), "r"(a[1]), "r"(a[2]), "r"(a[3]), "r"(b[0]), "r"(b[1]));
}

// ---------------- tile load: ROWS x 64 fp16 (128 B rows), SW128, cp.async ----------------
template <int ROWS>
__device__ __forceinline__ void tile_cp(uint32_t dstbase, const __half* __restrict__ g,
                                        int ld, int row0, int k0, int tid) {
    #pragma unroll
    for (int it = 0; it < ROWS * 8 / NTHREADS; it++) {
        int x = it * NTHREADS + tid;
        int r = x >> 3, c8 = x & 7;
        cp16(dstbase + sw128((uint32_t)(r * 128 + c8 * 16)),
             g + (size_t)(row0 + r) * ld + k0 + c8 * 8);
    }
}

__device__ __forceinline__ void stage_load(
    uint32_t sbase,
    const __half* Ah, int lda, int arow,
    const __half* Bh, int ldb, int brow,
    int k0, int tid)
{
    tile_cp<BM>(sbase,          Ah, lda, arow, k0, tid);
    tile_cp<BN>(sbase + TILE_A, Bh, ldb, brow, k0, tid);
}

// ---------------- compute one 64-K chunk; warp tile 64x64, 8 warps (2m x 4n) ----------------
__device__ __forceinline__ void compute_chunk(uint32_t sstage, int wm, int wn, int lane,
                                              float (&acc)[4][8][4])
{
    const uint32_t aBase = sstage;
    const uint32_t bBase = sstage + TILE_A;
    const int rowSel = lane & 15;
    const int colSel = (lane >> 4) * 16;

    #pragma unroll
    for (int kk = 0; kk < 4; kk++) {
        uint32_t ah[4][4];
        #pragma unroll
        for (int mt = 0; mt < 4; mt++) {
            int row = wm * 64 + mt * 16 + rowSel;
            uint32_t off = sw128((uint32_t)(row * 128 + kk * 32 + colSel));
            ldsm4(ah[mt][0], ah[mt][1], ah[mt][2], ah[mt][3], aBase + off);
        }
        uint32_t bh[8][2];
        #pragma unroll
        for (int p = 0; p < 4; p++) {
            int row = wn * 64 + p * 16 + rowSel;
            uint32_t off = sw128((uint32_t)(row * 128 + kk * 32 + colSel));
            uint32_t r0, r1, r2, r3;
            ldsm4(r0, r1, r2, r3, bBase + off);
            bh[p * 2][0] = r0; bh[p * 2][1] = r2;
            bh[p * 2 + 1][0] = r1; bh[p * 2 + 1][1] = r3;
        }
        #pragma unroll
        for (int mt = 0; mt < 4; mt++)
            #pragma unroll
            for (int nt = 0; nt < 8; nt++)
                mma4(acc[mt][nt], ah[mt], bh[nt]);
    }
}

// ---------------- mainloop: 2-stage double buffer ----------------
__device__ __forceinline__ void gemm_main(
    const __half* Ah, int lda, int arow,
    const __half* Bh, int ldb, int brow,
    int nchunks, uint32_t smb, float (&acc)[4][8][4])
{
    constexpr uint32_t SB = TILE_A + TILE_BN;    // 48 KB
    const int tid = threadIdx.x;
    const int wid = tid >> 5;
    const int wm = wid >> 2;             // 0..1
    const int wn = wid & 3;              // 0..3
    const int lane = tid & 31;

    stage_load(smb,      Ah, lda, arow, Bh, ldb, brow, 0,  tid); cp_commit();
    stage_load(smb + SB, Ah, lda, arow, Bh, ldb, brow, KC, tid); cp_commit();

    for (int i = 0; i < nchunks; i++) {
        cp_wait<1>();
        __syncthreads();
        compute_chunk(smb + (uint32_t)(i & 1) * SB, wm, wn, lane, acc);
        __syncthreads();
        if (i + 2 < nchunks)
            stage_load(smb + (uint32_t)(i & 1) * SB,
                       Ah, lda, arow, Bh, ldb, brow, (i + 2) * KC, tid);
        cp_commit();
    }
    __syncthreads();
}

// epilogue: accum fragments -> padded fp32 smem tile (row-major, pitch 260)
#define EPITCH 260
__device__ __forceinline__ void acc_to_smem(float* sf, int tid, float (&acc)[4][8][4])
{
    const int wid = tid >> 5;
    const int wm = wid >> 2;
    const int wn = wid & 3;
    const int lane = tid & 31;
    #pragma unroll
    for (int mt = 0; mt < 4; mt++)
        #pragma unroll
        for (int nt = 0; nt < 8; nt++) {
            int r = wm * 64 + mt * 16 + (lane >> 2);
            int c = wn * 64 + nt * 8 + (lane & 3) * 2;
            *reinterpret_cast<float2*>(&sf[r * EPITCH + c]) =
                make_float2(acc[mt][nt][0], acc[mt][nt][1]);
            *reinterpret_cast<float2*>(&sf[(r + 8) * EPITCH + c]) =
                make_float2(acc[mt][nt][2], acc[mt][nt][3]);
        }
}

#define GEMM_PROLOGUE()                                                 \
    extern __shared__ char smraw[];                                     \
    const uint32_t smb = (smem_u32(smraw) + 1023u) & ~1023u;            \
    char* smA = smraw + (smb - smem_u32(smraw));                        \
    const int tid = threadIdx.x;                                        \
    float acc[4][8][4];                                                 \
    _Pragma("unroll")                                                   \
    for (int i_ = 0; i_ < 4; i_++)                                      \
        _Pragma("unroll")                                               \
        for (int j_ = 0; j_ < 8; j_++)                                  \
            _Pragma("unroll")                                           \
            for (int k_ = 0; k_ < 4; k_++) acc[i_][j_][k_] = 0.f;

// ---------------- K1: QKV projection, single-term (z: 0=Q, 1=K, 2=V^T) ----------------
__global__ __launch_bounds__(NTHREADS, 1) void qkv_mma()
{
    GEMM_PROLOGUE();
    const int n0 = blockIdx.x * BN;
    const int m0 = blockIdx.y * BM;
    const int z  = blockIdx.z;

    gemm_main(g_xh, HID, m0,
              g_wh + (size_t)z * HID * HID, HID, n0,
              HID / KC, smb, acc);

    float* sf = reinterpret_cast<float*>(smA);
    acc_to_smem(sf, tid, acc);
    __syncthreads();

    if (z < 2) {
        __half* dst = (z == 0) ? g_qh : g_kh;
        #pragma unroll
        for (int it = 0; it < 64; it++) {
            int e = it * NTHREADS + tid;
            int c2 = e & 127, r = e >> 7;
            int c = 2 * c2;
            __half2 hv;
            hv.x = __float2half(sf[r * EPITCH + c]);
            hv.y = __float2half(sf[r * EPITCH + c + 1]);
            *reinterpret_cast<__half2*>(&dst[(size_t)(m0 + r) * HID + n0 + c]) = hv;
        }
    } else {
        const int b  = m0 / SEQ;
        const int s0 = m0 % SEQ;
        #pragma unroll
        for (int it = 0; it < 64; it++) {
            int e = it * NTHREADS + tid;
            int r2 = e & 63, c = e >> 6;            // c: 0..255
            __half2 hv;
            hv.x = __float2half(sf[(2 * r2) * EPITCH + c]);
            hv.y = __float2half(sf[(2 * r2 + 1) * EPITCH + c]);
            size_t base = ((size_t)b * HID + n0 + c) * SEQ + s0 + 2 * r2;
            *reinterpret_cast<__half2*>(&g_vth[base]) = hv;
        }
    }
}

// ---------------- K2: scores = (Q K^T)/32, single-term, causal tile skip ----------------
__global__ __launch_bounds__(NTHREADS, 1) void scores_mma()
{
    const int n0 = blockIdx.x * BN;
    const int m0 = ((int)gridDim.y - 1 - (int)blockIdx.y) * BM;  // descending work order
    if (n0 >= m0 + BM) return;           // fully masked tile
    const int b = blockIdx.z;

    GEMM_PROLOGUE();

    gemm_main(g_qh + (size_t)b * SEQ * HID, HID, m0,
              g_kh + (size_t)b * SEQ * HID, HID, n0,
              HID / KC, smb, acc);

    float* sf = reinterpret_cast<float*>(smA);
    acc_to_smem(sf, tid, acc);
    __syncthreads();

    float* dst = g_s + (size_t)b * SEQ * SEQ;
    #pragma unroll
    for (int it = 0; it < 128; it++) {
        int e = it * NTHREADS + tid;
        int c = e & 255, r = e >> 8;
        dst[(size_t)(m0 + r) * SEQ + n0 + c] = sf[r * EPITCH + c] * 0.03125f;
    }
}

// ---------------- K3: softmax; emits P as fp16 + zero pad to tile boundary ----------------
__global__ __launch_bounds__(128) void softmax_kernel()
{
    const int r = blockIdx.x;
    const int b = blockIdx.y;
    const size_t off = (size_t)b * SEQ * SEQ + (size_t)r * SEQ;
    const float* row = g_s + off;
    const int L = r + 1;
    const int t = threadIdx.x;

    float vals[32];
    int cnt = 0;
    float m = -1e30f;
    for (int k = t; k < L; k += 128) {
        float v = row[k];
        vals[cnt++] = v;
        m = fmaxf(m, v);
    }

    __shared__ float red[4];
    #pragma unroll
    for (int o = 16; o; o >>= 1) m = fmaxf(m, __shfl_xor_sync(0xffffffffu, m, o));
    if ((t & 31) == 0) red[t >> 5] = m;
    __syncthreads();
    m = fmaxf(fmaxf(red[0], red[1]), fmaxf(red[2], red[3]));
    __syncthreads();

    float s = 0.f;
    for (int i = 0; i < cnt; i++) {
        float e = __expf(vals[i] - m);
        vals[i] = e;
        s += e;
    }
    #pragma unroll
    for (int o = 16; o; o >>= 1) s += __shfl_xor_sync(0xffffffffu, s, o);
    if ((t & 31) == 0) red[t >> 5] = s;
    __syncthreads();
    s = red[0] + red[1] + red[2] + red[3];

    const float inv = 1.0f / s;
    cnt = 0;
    for (int k = t; k < L; k += 128)
        g_ph[off + k] = __float2half(vals[cnt++] * inv);

    const __half z = __float2half(0.f);
    const int Lpad = (r & ~(BM - 1)) + BM;
    for (int k = L + t; k < Lpad; k += 128)
        g_ph[off + k] = z;
}

// ---------------- K4: O = P V (single-term), K truncated at causal boundary ----------------
__global__ __launch_bounds__(NTHREADS, 1) void pv_mma(float* __restrict__ out)
{
    GEMM_PROLOGUE();
    const int n0 = blockIdx.x * BN;
    const int m0 = ((int)gridDim.y - 1 - (int)blockIdx.y) * BM;  // big tiles first
    const int b  = blockIdx.z;
    const int nchunks = (m0 + BM) / KC;

    gemm_main(g_ph + (size_t)b * SEQ * SEQ, SEQ, m0,
              g_vth + (size_t)b * HID * SEQ, SEQ, n0,
              nchunks, smb, acc);

    float* sf = reinterpret_cast<float*>(smA);
    acc_to_smem(sf, tid, acc);
    __syncthreads();

    float* dst = out + (size_t)b * SEQ * HID;
    #pragma unroll
    for (int it = 0; it < 128; it++) {
        int e = it * NTHREADS + tid;
        int c = e & 255, r = e >> 8;
        dst[(size_t)(m0 + r) * HID + n0 + c] = sf[r * EPITCH + c];
    }
}

// ---------------- K0: fp32 -> fp16 truncate (round-nearest) ----------------
__global__ __launch_bounds__(256) void convert_trunc_kernel(const float* __restrict__ src,
                                                            __half* __restrict__ hi, int n)
{
    int i = (blockIdx.x * 256 + threadIdx.x) * 4;
    if (i >= n) return;
    float4 v = *reinterpret_cast<const float4*>(src + i);
    __half2 h0, h1;
    h0.x = __float2half(v.x); h0.y = __float2half(v.y);
    h1.x = __float2half(v.z); h1.y = __float2half(v.w);
    *reinterpret_cast<__half2*>(hi + i)     = h0;
    *reinterpret_cast<__half2*>(hi + i + 2) = h1;
}

// ---------------- launch ----------------
extern "C" void kernel_launch(void* const* d_in, const int* in_sizes, int n_in,
                              void* d_out, int out_size)
{
    const float* x  = (const float*)d_in[0];
    const float* Wq = (const float*)d_in[1];
    const float* Wk = (const float*)d_in[2];
    const float* Wv = (const float*)d_in[3];
    float* out = (float*)d_out;

    cudaFuncSetAttribute(qkv_mma,    cudaFuncAttributeMaxDynamicSharedMemorySize, DYN_SMEM);
    cudaFuncSetAttribute(scores_mma, cudaFuncAttributeMaxDynamicSharedMemorySize, DYN_SMEM);
    cudaFuncSetAttribute(pv_mma,     cudaFuncAttributeMaxDynamicSharedMemorySize, DYN_SMEM);

    __half *xh, *wh;
    cudaGetSymbolAddress((void**)&xh, g_xh);
    cudaGetSymbolAddress((void**)&wh, g_wh);

    const int nx = MTOT * HID;
    const int nw = HID * HID;
    convert_trunc_kernel<<<nx / 1024, 256>>>(x,  xh,                  nx);
    convert_trunc_kernel<<<nw / 1024, 256>>>(Wq, wh,                  nw);
    convert_trunc_kernel<<<nw / 1024, 256>>>(Wk, wh + (size_t)nw,     nw);
    convert_trunc_kernel<<<nw / 1024, 256>>>(Wv, wh + 2 * (size_t)nw, nw);

    qkv_mma<<<dim3(HID / BN, MTOT / BM, 3), NTHREADS, DYN_SMEM>>>();
    scores_mma<<<dim3(SEQ / BN, SEQ / BM, BATCH), NTHREADS, DYN_SMEM>>>();
    softmax_kernel<<<dim3(SEQ, BATCH), 128>>>();
    pv_mma<<<dim3(HID / BN, SEQ / BM, BATCH), NTHREADS, DYN_SMEM>>>(out);
}

// round 17
// speedup vs baseline: 2.3260x; 1.0032x over previous
#include <cuda_runtime.h>
#include <cuda_fp16.h>
#include <cstdint>
#include <cstddef>

#define SEQ   4096
#define HID   1024
#define BATCH 4
#define MTOT  (BATCH * SEQ)

#define KC 64                            // K elements per chunk
#define BM 128                           // CTA tile M
#define BN 256                           // CTA tile N
#define TILE_A (BM * KC * 2)             // 16 KB (A tile)
#define TILE_BN (BN * KC * 2)            // 32 KB (B tile)
#define EPI_BYTES (BM * 260 * 4)         // 133,120 B fp32 epilogue tile
#define DYN_SMEM (EPI_BYTES + 1024)      // >= 2*(TILE_A+TILE_BN)=96K too
#define NTHREADS 256

// ---------------- scratch (device globals; no runtime alloc) ----------------
__device__ __half g_xh[(size_t)MTOT * HID];                       // x truncated
__device__ __half g_wh[(size_t)3 * HID * HID];                    // W truncated
__device__ __half g_qh[(size_t)MTOT * HID];                       // Q truncated
__device__ __half g_kh[(size_t)MTOT * HID];                       // K truncated
__device__ __half g_vth[(size_t)MTOT * HID];                      // V^T truncated [b][h][s]
__device__ float  g_s[(size_t)BATCH * SEQ * SEQ];
__device__ __half g_ph[(size_t)BATCH * SEQ * SEQ];                // P truncated

// ---------------- helpers (base-target PTX only) ----------------
__device__ __forceinline__ uint32_t smem_u32(const void* p) {
    return (uint32_t)__cvta_generic_to_shared(p);
}
__device__ __forceinline__ uint32_t sw128(uint32_t o) { return o ^ ((o >> 3) & 0x70); }

__device__ __forceinline__ void cp16(uint32_t dst, const void* src) {
    asm volatile("cp.async.cg.shared.global [%0], [%1], 16;" :: "r"(dst), "l"(src) : "memory");
}
__device__ __forceinline__ void cp_commit() {
    asm volatile("cp.async.commit_group;" ::: "memory");
}
template <int N>
__device__ __forceinline__ void cp_wait() {
    asm volatile("cp.async.wait_group %0;" :: "n"(N) : "memory");
}
__device__ __forceinline__ void ldsm4(uint32_t& r0, uint32_t& r1, uint32_t& r2, uint32_t& r3,
                                      uint32_t addr) {
    asm volatile("ldmatrix.sync.aligned.m8n8.x4.shared.b16 {%0,%1,%2,%3}, [%4];"
                 : "=r"(r0), "=r"(r1), "=r"(r2), "=r"(r3) : "r"(addr));
}
__device__ __forceinline__ void mma4(float (&d)[4], const uint32_t (&a)[4], const uint32_t (&b)[2]) {
    asm volatile(
        "mma.sync.aligned.m16n8k16.row.col.f32.f16.f16.f32 "
        "{%0,%1,%2,%3}, {%4,%5,%6,%7}, {%8,%9}, {%0,%1,%2,%3};"
        : "+f"(d[0]), "+f"(d[1]), "+f"(d[2]), "+f"(d[3])
        : "r"(a[0]), "r"(a[1]), "r"(a[2]), "r"(a[3]), "r"(b[0]), "r"(b[1]));
}

// ---------------- tile load: ROWS x 64 fp16 (128 B rows), SW128, cp.async ----------------
template <int ROWS>
__device__ __forceinline__ void tile_cp(uint32_t dstbase, const __half* __restrict__ g,
                                        int ld, int row0, int k0, int tid) {
    #pragma unroll
    for (int it = 0; it < ROWS * 8 / NTHREADS; it++) {
        int x = it * NTHREADS + tid;
        int r = x >> 3, c8 = x & 7;
        cp16(dstbase + sw128((uint32_t)(r * 128 + c8 * 16)),
             g + (size_t)(row0 + r) * ld + k0 + c8 * 8);
    }
}

__device__ __forceinline__ void stage_load(
    uint32_t sbase,
    const __half* Ah, int lda, int arow,
    const __half* Bh, int ldb, int brow,
    int k0, int tid)
{
    tile_cp<BM>(sbase,          Ah, lda, arow, k0, tid);
    tile_cp<BN>(sbase + TILE_A, Bh, ldb, brow, k0, tid);
}

// ---------------- compute one 64-K chunk; warp tile 64x64, 8 warps (2m x 4n) ----------------
__device__ __forceinline__ void compute_chunk(uint32_t sstage, int wm, int wn, int lane,
                                              float (&acc)[4][8][4])
{
    const uint32_t aBase = sstage;
    const uint32_t bBase = sstage + TILE_A;
    const int rowSel = lane & 15;
    const int colSel = (lane >> 4) * 16;

    #pragma unroll
    for (int kk = 0; kk < 4; kk++) {
        uint32_t ah[4][4];
        #pragma unroll
        for (int mt = 0; mt < 4; mt++) {
            int row = wm * 64 + mt * 16 + rowSel;
            uint32_t off = sw128((uint32_t)(row * 128 + kk * 32 + colSel));
            ldsm4(ah[mt][0], ah[mt][1], ah[mt][2], ah[mt][3], aBase + off);
        }
        uint32_t bh[8][2];
        #pragma unroll
        for (int p = 0; p < 4; p++) {
            int row = wn * 64 + p * 16 + rowSel;
            uint32_t off = sw128((uint32_t)(row * 128 + kk * 32 + colSel));
            uint32_t r0, r1, r2, r3;
            ldsm4(r0, r1, r2, r3, bBase + off);
            bh[p * 2][0] = r0; bh[p * 2][1] = r2;
            bh[p * 2 + 1][0] = r1; bh[p * 2 + 1][1] = r3;
        }
        #pragma unroll
        for (int mt = 0; mt < 4; mt++)
            #pragma unroll
            for (int nt = 0; nt < 8; nt++)
                mma4(acc[mt][nt], ah[mt], bh[nt]);
    }
}

// ---------------- mainloop: 2-stage double buffer ----------------
__device__ __forceinline__ void gemm_main(
    const __half* Ah, int lda, int arow,
    const __half* Bh, int ldb, int brow,
    int nchunks, uint32_t smb, float (&acc)[4][8][4])
{
    constexpr uint32_t SB = TILE_A + TILE_BN;    // 48 KB
    const int tid = threadIdx.x;
    const int wid = tid >> 5;
    const int wm = wid >> 2;             // 0..1
    const int wn = wid & 3;              // 0..3
    const int lane = tid & 31;

    stage_load(smb,      Ah, lda, arow, Bh, ldb, brow, 0,  tid); cp_commit();
    stage_load(smb + SB, Ah, lda, arow, Bh, ldb, brow, KC, tid); cp_commit();

    for (int i = 0; i < nchunks; i++) {
        cp_wait<1>();
        __syncthreads();
        compute_chunk(smb + (uint32_t)(i & 1) * SB, wm, wn, lane, acc);
        __syncthreads();
        if (i + 2 < nchunks)
            stage_load(smb + (uint32_t)(i & 1) * SB,
                       Ah, lda, arow, Bh, ldb, brow, (i + 2) * KC, tid);
        cp_commit();
    }
    __syncthreads();
}

// epilogue: accum fragments -> padded fp32 smem tile (row-major, pitch 260)
#define EPITCH 260
__device__ __forceinline__ void acc_to_smem(float* sf, int tid, float (&acc)[4][8][4])
{
    const int wid = tid >> 5;
    const int wm = wid >> 2;
    const int wn = wid & 3;
    const int lane = tid & 31;
    #pragma unroll
    for (int mt = 0; mt < 4; mt++)
        #pragma unroll
        for (int nt = 0; nt < 8; nt++) {
            int r = wm * 64 + mt * 16 + (lane >> 2);
            int c = wn * 64 + nt * 8 + (lane & 3) * 2;
            *reinterpret_cast<float2*>(&sf[r * EPITCH + c]) =
                make_float2(acc[mt][nt][0], acc[mt][nt][1]);
            *reinterpret_cast<float2*>(&sf[(r + 8) * EPITCH + c]) =
                make_float2(acc[mt][nt][2], acc[mt][nt][3]);
        }
}

#define GEMM_PROLOGUE()                                                 \
    extern __shared__ char smraw[];                                     \
    const uint32_t smb = (smem_u32(smraw) + 1023u) & ~1023u;            \
    char* smA = smraw + (smb - smem_u32(smraw));                        \
    const int tid = threadIdx.x;                                        \
    float acc[4][8][4];                                                 \
    _Pragma("unroll")                                                   \
    for (int i_ = 0; i_ < 4; i_++)                                      \
        _Pragma("unroll")                                               \
        for (int j_ = 0; j_ < 8; j_++)                                  \
            _Pragma("unroll")                                           \
            for (int k_ = 0; k_ < 4; k_++) acc[i_][j_][k_] = 0.f;

// ---------------- K1: QKV projection, single-term (z: 0=Q, 1=K, 2=V^T) ----------------
__global__ __launch_bounds__(NTHREADS, 1) void qkv_mma()
{
    GEMM_PROLOGUE();
    const int n0 = blockIdx.x * BN;
    const int m0 = blockIdx.y * BM;
    const int z  = blockIdx.z;

    gemm_main(g_xh, HID, m0,
              g_wh + (size_t)z * HID * HID, HID, n0,
              HID / KC, smb, acc);

    float* sf = reinterpret_cast<float*>(smA);
    acc_to_smem(sf, tid, acc);
    __syncthreads();

    if (z < 2) {
        __half* dst = (z == 0) ? g_qh : g_kh;
        #pragma unroll
        for (int it = 0; it < 64; it++) {
            int e = it * NTHREADS + tid;
            int c2 = e & 127, r = e >> 7;
            int c = 2 * c2;
            __half2 hv;
            hv.x = __float2half(sf[r * EPITCH + c]);
            hv.y = __float2half(sf[r * EPITCH + c + 1]);
            *reinterpret_cast<__half2*>(&dst[(size_t)(m0 + r) * HID + n0 + c]) = hv;
        }
    } else {
        const int b  = m0 / SEQ;
        const int s0 = m0 % SEQ;
        #pragma unroll
        for (int it = 0; it < 64; it++) {
            int e = it * NTHREADS + tid;
            int r2 = e & 63, c = e >> 6;            // c: 0..255
            __half2 hv;
            hv.x = __float2half(sf[(2 * r2) * EPITCH + c]);
            hv.y = __float2half(sf[(2 * r2 + 1) * EPITCH + c]);
            size_t base = ((size_t)b * HID + n0 + c) * SEQ + s0 + 2 * r2;
            *reinterpret_cast<__half2*>(&g_vth[base]) = hv;
        }
    }
}

// ---------------- K2: scores = (Q K^T)/32, single-term, causal tile skip ----------------
__global__ __launch_bounds__(NTHREADS, 1) void scores_mma()
{
    const int n0 = blockIdx.x * BN;
    const int m0 = ((int)gridDim.y - 1 - (int)blockIdx.y) * BM;  // descending work order
    if (n0 >= m0 + BM) return;           // fully masked tile
    const int b = blockIdx.z;

    GEMM_PROLOGUE();

    gemm_main(g_qh + (size_t)b * SEQ * HID, HID, m0,
              g_kh + (size_t)b * SEQ * HID, HID, n0,
              HID / KC, smb, acc);

    float* sf = reinterpret_cast<float*>(smA);
    acc_to_smem(sf, tid, acc);
    __syncthreads();

    float* dst = g_s + (size_t)b * SEQ * SEQ;
    #pragma unroll
    for (int it = 0; it < 128; it++) {
        int e = it * NTHREADS + tid;
        int c = e & 255, r = e >> 8;
        dst[(size_t)(m0 + r) * SEQ + n0 + c] = sf[r * EPITCH + c] * 0.03125f;
    }
}

// ---------------- K3: softmax (vectorized); emits P as fp16 + zero pad ----------------
__global__ __launch_bounds__(128) void softmax_kernel()
{
    const int r = blockIdx.x;
    const int b = blockIdx.y;
    const size_t off = (size_t)b * SEQ * SEQ + (size_t)r * SEQ;
    const float* row = g_s + off;
    const int L = r + 1;
    const int t = threadIdx.x;
    const int nvec = L >> 2;                 // # of full float4 groups

    float4 vals[8];
    int cnt = 0;
    float m = -1e30f;
    for (int i = t; i < nvec; i += 128) {
        float4 v = reinterpret_cast<const float4*>(row)[i];
        vals[cnt++] = v;
        m = fmaxf(m, fmaxf(fmaxf(v.x, v.y), fmaxf(v.z, v.w)));
    }
    const int tidx = (nvec << 2) + t;
    const bool hastail = tidx < L;
    float tailv = 0.f;
    if (hastail) { tailv = row[tidx]; m = fmaxf(m, tailv); }

    __shared__ float red[4];
    #pragma unroll
    for (int o = 16; o; o >>= 1) m = fmaxf(m, __shfl_xor_sync(0xffffffffu, m, o));
    if ((t & 31) == 0) red[t >> 5] = m;
    __syncthreads();
    m = fmaxf(fmaxf(red[0], red[1]), fmaxf(red[2], red[3]));
    __syncthreads();

    float s = 0.f;
    for (int i = 0; i < cnt; i++) {
        float4 v = vals[i];
        v.x = __expf(v.x - m); v.y = __expf(v.y - m);
        v.z = __expf(v.z - m); v.w = __expf(v.w - m);
        vals[i] = v;
        s += (v.x + v.y) + (v.z + v.w);
    }
    float tailE = 0.f;
    if (hastail) { tailE = __expf(tailv - m); s += tailE; }

    #pragma unroll
    for (int o = 16; o; o >>= 1) s += __shfl_xor_sync(0xffffffffu, s, o);
    if ((t & 31) == 0) red[t >> 5] = s;
    __syncthreads();
    s = red[0] + red[1] + red[2] + red[3];

    const float inv = 1.0f / s;
    __half* ph = g_ph + off;
    cnt = 0;
    for (int i = t; i < nvec; i += 128) {
        float4 v = vals[cnt++];
        __half2 h0, h1;
        h0.x = __float2half(v.x * inv); h0.y = __float2half(v.y * inv);
        h1.x = __float2half(v.z * inv); h1.y = __float2half(v.w * inv);
        uint2 pk;
        pk.x = *reinterpret_cast<uint32_t*>(&h0);
        pk.y = *reinterpret_cast<uint32_t*>(&h1);
        *reinterpret_cast<uint2*>(ph + (i << 2)) = pk;
    }
    if (hastail) ph[tidx] = __float2half(tailE * inv);

    const __half z = __float2half(0.f);
    const int Lpad = (r & ~(BM - 1)) + BM;
    for (int k = L + t; k < Lpad; k += 128)
        ph[k] = z;
}

// ---------------- K4: O = P V (single-term), K truncated at causal boundary ----------------
__global__ __launch_bounds__(NTHREADS, 1) void pv_mma(float* __restrict__ out)
{
    GEMM_PROLOGUE();
    const int n0 = blockIdx.x * BN;
    const int m0 = ((int)gridDim.y - 1 - (int)blockIdx.y) * BM;  // big tiles first
    const int b  = blockIdx.z;
    const int nchunks = (m0 + BM) / KC;

    gemm_main(g_ph + (size_t)b * SEQ * SEQ, SEQ, m0,
              g_vth + (size_t)b * HID * SEQ, SEQ, n0,
              nchunks, smb, acc);

    float* sf = reinterpret_cast<float*>(smA);
    acc_to_smem(sf, tid, acc);
    __syncthreads();

    float* dst = out + (size_t)b * SEQ * HID;
    #pragma unroll
    for (int it = 0; it < 128; it++) {
        int e = it * NTHREADS + tid;
        int c = e & 255, r = e >> 8;
        dst[(size_t)(m0 + r) * HID + n0 + c] = sf[r * EPITCH + c];
    }
}

// ---------------- K0a: fp32 -> fp16 truncate (x) ----------------
__global__ __launch_bounds__(256) void convert_trunc_kernel(const float* __restrict__ src,
                                                            __half* __restrict__ hi, int n)
{
    int i = (blockIdx.x * 256 + threadIdx.x) * 4;
    if (i >= n) return;
    float4 v = *reinterpret_cast<const float4*>(src + i);
    __half2 h0, h1;
    h0.x = __float2half(v.x); h0.y = __float2half(v.y);
    h1.x = __float2half(v.z); h1.y = __float2half(v.w);
    *reinterpret_cast<__half2*>(hi + i)     = h0;
    *reinterpret_cast<__half2*>(hi + i + 2) = h1;
}

// ---------------- K0b: all 3 weights in one launch (blockIdx.y selects) ----------------
__global__ __launch_bounds__(256) void convert_w_kernel(const float* __restrict__ Wq,
                                                        const float* __restrict__ Wk,
                                                        const float* __restrict__ Wv)
{
    const int z = blockIdx.y;
    const float* src = (z == 0) ? Wq : (z == 1) ? Wk : Wv;
    __half* dst = g_wh + (size_t)z * HID * HID;
    int i = (blockIdx.x * 256 + threadIdx.x) * 4;
    float4 v = *reinterpret_cast<const float4*>(src + i);
    __half2 h0, h1;
    h0.x = __float2half(v.x); h0.y = __float2half(v.y);
    h1.x = __float2half(v.z); h1.y = __float2half(v.w);
    *reinterpret_cast<__half2*>(dst + i)     = h0;
    *reinterpret_cast<__half2*>(dst + i + 2) = h1;
}

// ---------------- launch ----------------
extern "C" void kernel_launch(void* const* d_in, const int* in_sizes, int n_in,
                              void* d_out, int out_size)
{
    const float* x  = (const float*)d_in[0];
    const float* Wq = (const float*)d_in[1];
    const float* Wk = (const float*)d_in[2];
    const float* Wv = (const float*)d_in[3];
    float* out = (float*)d_out;

    cudaFuncSetAttribute(qkv_mma,    cudaFuncAttributeMaxDynamicSharedMemorySize, DYN_SMEM);
    cudaFuncSetAttribute(scores_mma, cudaFuncAttributeMaxDynamicSharedMemorySize, DYN_SMEM);
    cudaFuncSetAttribute(pv_mma,     cudaFuncAttributeMaxDynamicSharedMemorySize, DYN_SMEM);

    __half* xh;
    cudaGetSymbolAddress((void**)&xh, g_xh);

    const int nx = MTOT * HID;
    const int nw = HID * HID;
    convert_trunc_kernel<<<nx / 1024, 256>>>(x, xh, nx);
    convert_w_kernel<<<dim3(nw / 1024, 3), 256>>>(Wq, Wk, Wv);

    qkv_mma<<<dim3(HID / BN, MTOT / BM, 3), NTHREADS, DYN_SMEM>>>();
    scores_mma<<<dim3(SEQ / BN, SEQ / BM, BATCH), NTHREADS, DYN_SMEM>>>();
    softmax_kernel<<<dim3(SEQ, BATCH), 128>>>();
    pv_mma<<<dim3(HID / BN, SEQ / BM, BATCH), NTHREADS, DYN_SMEM>>>(out);
}